// round 16
// baseline (speedup 1.0000x reference)
#include <cuda_runtime.h>
#include <cuda_fp16.h>
#include <cstdint>
#include <cstddef>

#define NR 2048
#define NC 32
#define NO 32
#define NI 32
#define NB 64
#define NCO (NC*NO)        // 1024
#define RSTRIDE (NCO*NB)   // 65536 halves per route in u_hat
#define C_UNI (1.0f/2048.0f)
#define TPAD 72            // padded smem tile row stride (halves)
#define GC 8               // capsules per group (slice = 64 MB, fits L2)
#define NG 4               // number of groups

// Scratch (device globals: allocation-free contract)
__device__ __half g_uhat[(size_t)NR * NCO * NB]; // [r][c][o][b]  268 MB fp16
__device__ float  g_spart[64 * 8 * 256];         // per-group k_s partials 512KB
__device__ float  g_blog[NC * NR];               // routing logits b_ij [c][r]
__device__ float  g_cij[NC * NR];                // softmax(b) over r, [c][r]
__device__ float  g_v2[NCO * NB];                // v in [c][o][b] layout

// ---------------------------------------------------------------------------
__device__ __forceinline__ uint32_t pack_f16x2(float a, float b) {
    uint32_t r;
    asm("cvt.rn.f16x2.f32 %0, %1, %2;" : "=r"(r) : "f"(b), "f"(a));
    return r;
}
// D += A*B (m16n8k16, fp16 in, fp32 acc) — plain mma.sync
__device__ __forceinline__ void mma16816(float* c, const uint32_t* a,
                                         uint32_t b0, uint32_t b1) {
    asm volatile(
        "mma.sync.aligned.m16n8k16.row.col.f32.f16.f16.f32 "
        "{%0,%1,%2,%3},{%4,%5,%6,%7},{%8,%9},{%0,%1,%2,%3};"
        : "+f"(c[0]), "+f"(c[1]), "+f"(c[2]), "+f"(c[3])
        : "r"(a[0]), "r"(a[1]), "r"(a[2]), "r"(a[3]), "r"(b0), "r"(b1));
}

// ---------------------------------------------------------------------------
// u_hat slice for capsule group gp: per route r, warp w = capsule gp*8+w,
// 2 m16 o-tiles. W streamed with __ldcs (read-once; keep L2 for u slice).
// Coalesced store path via padded smem tile (R14 WIN).
__global__ void __launch_bounds__(256) k_uhat(const float* __restrict__ x,
                                              const float* __restrict__ W,
                                              int gp) {
    __shared__ __half tile[8][16 * TPAD];
    const int r    = blockIdx.x;
    const int tid  = threadIdx.x;
    const int w    = tid >> 5;
    const int lane = tid & 31;
    const int lg   = lane >> 2;
    const int tg   = lane & 3;

    uint32_t B[8][2][2];
#pragma unroll
    for (int nt = 0; nt < 8; ++nt) {
        const float* xr = x + (size_t)(nt * 8 + lg) * (NR * NI) + (size_t)r * NI;
#pragma unroll
        for (int ks = 0; ks < 2; ++ks) {
            const float2 v0 = *(const float2*)(xr + ks * 16 + 2 * tg);
            const float2 v1 = *(const float2*)(xr + ks * 16 + 2 * tg + 8);
            B[nt][ks][0] = pack_f16x2(v0.x, v0.y);
            B[nt][ks][1] = pack_f16x2(v1.x, v1.y);
        }
    }

    const float* wbase = W + (size_t)r * (NCO * NI);
    __half* const ubase = g_uhat + (size_t)r * RSTRIDE;
    const int cbase = (gp * GC + w) * NO;   // this warp's global co base

#pragma unroll
    for (int mt = 0; mt < 2; ++mt) {
        const int co0 = cbase + mt * 16 + lg;
        const float* wr0 = wbase + (size_t)co0 * NI;
        const float* wr1 = wr0 + 8 * NI;

        uint32_t A[2][4];
#pragma unroll
        for (int ks = 0; ks < 2; ++ks) {
            float2 v;
            v = __ldcs((const float2*)(wr0 + ks * 16 + 2 * tg));     A[ks][0] = pack_f16x2(v.x, v.y);
            v = __ldcs((const float2*)(wr1 + ks * 16 + 2 * tg));     A[ks][1] = pack_f16x2(v.x, v.y);
            v = __ldcs((const float2*)(wr0 + ks * 16 + 2 * tg + 8)); A[ks][2] = pack_f16x2(v.x, v.y);
            v = __ldcs((const float2*)(wr1 + ks * 16 + 2 * tg + 8)); A[ks][3] = pack_f16x2(v.x, v.y);
        }

        __half* const tw = tile[w];
#pragma unroll
        for (int nt = 0; nt < 8; ++nt) {
            float acc[4] = {0.f, 0.f, 0.f, 0.f};
            mma16816(acc, A[0], B[nt][0][0], B[nt][0][1]);
            mma16816(acc, A[1], B[nt][1][0], B[nt][1][1]);
            const int b0 = nt * 8 + 2 * tg;
            *(__half2*)(tw + lg * TPAD + b0)       = __floats2half2_rn(acc[0], acc[1]);
            *(__half2*)(tw + (lg + 8) * TPAD + b0) = __floats2half2_rn(acc[2], acc[3]);
        }
        __syncwarp();

        uint4* dst = (uint4*)(ubase + (size_t)(cbase + mt * 16) * NB);
#pragma unroll
        for (int p2 = 0; p2 < 4; ++p2) {
            const int e   = p2 * 32 + lane;
            const int row = e >> 3;
            const int col = e & 7;
            dst[e] = *(const uint4*)(tw + row * TPAD + col * 8);
        }
        __syncwarp();
    }
}

// ---------------------------------------------------------------------------
// c_ij[c][:] = softmax over r of b[c][:], for c in group gp.
__global__ void __launch_bounds__(256) k_softmax(int gp) {
    const int c   = gp * GC + blockIdx.x;
    const int tid = threadIdx.x;
    __shared__ float sm[8];
    const float* bp = g_blog + c * NR;

    float vals[8];
#pragma unroll
    for (int j = 0; j < 8; ++j) vals[j] = bp[tid + j * 256];

    float m = vals[0];
#pragma unroll
    for (int j = 1; j < 8; ++j) m = fmaxf(m, vals[j]);
#pragma unroll
    for (int off = 16; off; off >>= 1) m = fmaxf(m, __shfl_xor_sync(0xffffffffu, m, off));
    if ((tid & 31) == 0) sm[tid >> 5] = m;
    __syncthreads();
    float mm = sm[0];
#pragma unroll
    for (int j = 1; j < 8; ++j) mm = fmaxf(mm, sm[j]);
    __syncthreads();

    float e[8];
    float s = 0.f;
#pragma unroll
    for (int j = 0; j < 8; ++j) { e[j] = expf(vals[j] - mm); s += e[j]; }
#pragma unroll
    for (int off = 16; off; off >>= 1) s += __shfl_xor_sync(0xffffffffu, s, off);
    if ((tid & 31) == 0) sm[tid >> 5] = s;
    __syncthreads();
    float tot = 0.f;
#pragma unroll
    for (int j = 0; j < 8; ++j) tot += sm[j];
    const float inv = 1.f / tot;
    float* cp = g_cij + c * NR;
#pragma unroll
    for (int j = 0; j < 8; ++j) cp[tid + j * 256] = e[j] * inv;
}

// ---------------------------------------------------------------------------
// s partial for group gp: block (quad 0..63, q 0..7) covers co quad
// gp*64+quad and routes [q*256, +256). Warp = 32 routes; lane reads one
// uint4/route. Plain loads (want L2 hits on the group slice).
__global__ void __launch_bounds__(256) k_s(int uniform, int gp) {
    const int bx  = blockIdx.x;          // quad within group
    const int q   = blockIdx.y;          // route eighth
    const int c   = gp * GC + (bx >> 3);
    const int tid = threadIdx.x;
    __shared__ float cs[256];
    __shared__ float red[8][256];

    if (!uniform) {
        cs[tid] = g_cij[c * NR + q * 256 + tid];
        __syncthreads();
    }

    const int seg  = tid >> 5;
    const int lane = tid & 31;
    const int r0   = q * 256 + seg * 32;
    const int co4g = gp * 64 + bx;
    const uint4* p = (const uint4*)(g_uhat + (size_t)r0 * RSTRIDE)
                     + co4g * 32 + lane;
    const float* csp = cs + seg * 32;

    float acc[8] = {0.f, 0.f, 0.f, 0.f, 0.f, 0.f, 0.f, 0.f};
#pragma unroll 16
    for (int k = 0; k < 32; ++k) {
        const uint4 u = p[(size_t)k * (RSTRIDE / 8)];
        const float cc = uniform ? C_UNI : csp[k];
        const float2 f0 = __half22float2(*(const __half2*)&u.x);
        const float2 f1 = __half22float2(*(const __half2*)&u.y);
        const float2 f2 = __half22float2(*(const __half2*)&u.z);
        const float2 f3 = __half22float2(*(const __half2*)&u.w);
        acc[0] = fmaf(cc, f0.x, acc[0]);
        acc[1] = fmaf(cc, f0.y, acc[1]);
        acc[2] = fmaf(cc, f1.x, acc[2]);
        acc[3] = fmaf(cc, f1.y, acc[3]);
        acc[4] = fmaf(cc, f2.x, acc[4]);
        acc[5] = fmaf(cc, f2.y, acc[5]);
        acc[6] = fmaf(cc, f3.x, acc[6]);
        acc[7] = fmaf(cc, f3.y, acc[7]);
    }
    *(float4*)&red[seg][lane * 8]     = make_float4(acc[0], acc[1], acc[2], acc[3]);
    *(float4*)&red[seg][lane * 8 + 4] = make_float4(acc[4], acc[5], acc[6], acc[7]);
    __syncthreads();

    float s = 0.f;
#pragma unroll
    for (int j = 0; j < 8; ++j) s += red[j][tid];
    g_spart[(bx * 8 + q) * 256 + tid] = s;
}

// ---------------------------------------------------------------------------
// Combine eighths, squash -> g_v2 slice (+ final output on last iteration).
__global__ void __launch_bounds__(256) k_red(float* __restrict__ outp, int gp) {
    const int bx = blockIdx.x;           // quad within group
    const int e  = threadIdx.x;
    const float* pp = g_spart + bx * 8 * 256 + e;
    float s = 0.f;
#pragma unroll
    for (int q = 0; q < 8; ++q) s += pp[q * 256];
    const int co = (gp * 64 + bx) * 4 + (e >> 6);
    const int b  = e & 63;
    const float sq = s * s;
    const float v  = sq * s / ((1.f + sq) * sqrtf(sq));
    g_v2[co * NB + b] = v;
    if (outp) outp[b * NCO + co] = v;
}

// ---------------------------------------------------------------------------
// b[c][r] (+)= (1/B) * sum_{b,o} u_hat[r][c][o][b] * v[c][o][b], c in group.
// Warp = (rg of 16 routes, o-quarter); 2-deep pipeline; plain loads (L2 hits).
__global__ void __launch_bounds__(256) k_a(int first, int gp) {
    const int c    = gp * GC + blockIdx.y;
    const int r0   = blockIdx.x * 32;
    const int tid  = threadIdx.x;
    const int lane = tid & 31;
    const int w    = tid >> 5;
    const int oq   = w & 3;
    const int rg   = w >> 2;
    __shared__ __align__(16) float vsm[NO * NB];  // 8 KB
    __shared__ float a_sm[32];

    const float4* vsrc = (const float4*)(g_v2 + c * (NO * NB));
    float4* vdst = (float4*)vsm;
#pragma unroll
    for (int j = 0; j < 2; ++j) vdst[tid + j * 256] = vsrc[tid + j * 256];
    if (tid < 32) a_sm[tid] = 0.f;
    __syncthreads();

    float4 vr[4];
#pragma unroll
    for (int k = 0; k < 2; ++k) {
        const int s = oq * 64 + k * 32 + lane;
        vr[2 * k]     = ((const float4*)vsm)[2 * s];
        vr[2 * k + 1] = ((const float4*)vsm)[2 * s + 1];
    }

    const uint4* const ubase =
        (const uint4*)(g_uhat + (size_t)r0 * RSTRIDE + c * (NO * NB))
        + oq * 64 + lane;
    const size_t rstep = RSTRIDE / 8;

    uint4 u0 = ubase[(size_t)(rg * 16) * rstep];
    uint4 u1 = ubase[(size_t)(rg * 16) * rstep + 32];

#pragma unroll 4
    for (int it = 0; it < 16; ++it) {
        const int rl = rg * 16 + it;
        uint4 n0, n1;
        if (it < 15) {
            n0 = ubase[(size_t)(rl + 1) * rstep];
            n1 = ubase[(size_t)(rl + 1) * rstep + 32];
        }
        float p = 0.f;
        {
            const float2 f0 = __half22float2(*(const __half2*)&u0.x);
            const float2 f1 = __half22float2(*(const __half2*)&u0.y);
            const float2 f2 = __half22float2(*(const __half2*)&u0.z);
            const float2 f3 = __half22float2(*(const __half2*)&u0.w);
            p = fmaf(f0.x, vr[0].x, p); p = fmaf(f0.y, vr[0].y, p);
            p = fmaf(f1.x, vr[0].z, p); p = fmaf(f1.y, vr[0].w, p);
            p = fmaf(f2.x, vr[1].x, p); p = fmaf(f2.y, vr[1].y, p);
            p = fmaf(f3.x, vr[1].z, p); p = fmaf(f3.y, vr[1].w, p);
        }
        {
            const float2 f0 = __half22float2(*(const __half2*)&u1.x);
            const float2 f1 = __half22float2(*(const __half2*)&u1.y);
            const float2 f2 = __half22float2(*(const __half2*)&u1.z);
            const float2 f3 = __half22float2(*(const __half2*)&u1.w);
            p = fmaf(f0.x, vr[2].x, p); p = fmaf(f0.y, vr[2].y, p);
            p = fmaf(f1.x, vr[2].z, p); p = fmaf(f1.y, vr[2].w, p);
            p = fmaf(f2.x, vr[3].x, p); p = fmaf(f2.y, vr[3].y, p);
            p = fmaf(f3.x, vr[3].z, p); p = fmaf(f3.y, vr[3].w, p);
        }
        u0 = n0; u1 = n1;
#pragma unroll
        for (int off = 16; off; off >>= 1) p += __shfl_xor_sync(0xffffffffu, p, off);
        if (lane == 0) atomicAdd(&a_sm[rl], p);
    }
    __syncthreads();

    if (tid < 32) {
        const float val = a_sm[tid] * (1.f / NB);
        if (first) g_blog[c * NR + r0 + tid] = val;
        else       g_blog[c * NR + r0 + tid] += val;
    }
}

// ---------------------------------------------------------------------------
extern "C" void kernel_launch(void* const* d_in, const int* in_sizes, int n_in,
                              void* d_out, int out_size) {
    const float* x = (const float*)d_in[0];  // [B, R, I]
    const float* W = (const float*)d_in[1];  // [R, C, O, I]
    if (n_in >= 2 && in_sizes[0] > in_sizes[1]) {  // robust to input ordering
        const float* t = x; x = W; W = t;
    }
    float* out = (float*)d_out;

    // Per capsule group: u_hat slice (64 MB, L2-resident) + all 3 routing
    // iterations on that slice. Routing is fully independent per capsule.
    for (int gp = 0; gp < NG; ++gp) {
        k_uhat<<<NR, 256>>>(x, W, gp);

        // iteration 0: softmax(0) == exactly 1/2048
        k_s<<<dim3(64, 8), 256>>>(1, gp);
        k_red<<<64, 256>>>(nullptr, gp);
        k_a<<<dim3(64, GC), 256>>>(1, gp);

        // iteration 1
        k_softmax<<<GC, 256>>>(gp);
        k_s<<<dim3(64, 8), 256>>>(0, gp);
        k_red<<<64, 256>>>(nullptr, gp);
        k_a<<<dim3(64, GC), 256>>>(0, gp);

        // iteration 2 (final)
        k_softmax<<<GC, 256>>>(gp);
        k_s<<<dim3(64, 8), 256>>>(0, gp);
        k_red<<<64, 256>>>(out, gp);
    }
}